// round 9
// baseline (speedup 1.0000x reference)
#include <cuda_runtime.h>

#define SDIM 1024
#define NROW (SDIM*SDIM)
#define NCOL 2048
#define NBAND 7
#define CYCLES 10
#define SMOOTHS 3
#define COARSE_IT 10

// ---------------- device scratch (no allocation allowed) ----------------
__device__ float g_bufA[NROW];
__device__ float g_bufB[NROW];
__device__ float g_band[NCOL * NBAND];
__device__ float g_rc0[NCOL];
__device__ float g_rc1[NCOL];
__device__ float g_ec[NCOL];

// W = 2/3 (rounded to f32 like the reference), fine dinv = 1/4 exactly
#define WJ ((float)(2.0/3.0))
#define WDI (WJ * 0.25f)

// Buffer selectors: 0 = external input x0, 1 = g_bufA, 2 = g_bufB, 3 = external out
__device__ __forceinline__ const float* sel_src(int s, const float* x0, const float* out) {
    if (s == 0) return x0;
    if (s == 1) return g_bufA;
    if (s == 2) return g_bufB;
    return out;
}
__device__ __forceinline__ float* sel_dst(int s, float* out) {
    if (s == 1) return g_bufA;
    if (s == 2) return g_bufB;
    return out;
}

// ---------------- fine-grid weighted Jacobi sweep ----------------
// x_out = x_in + (W/4) * (b - A x_in), A = 5-point Laplacian (diag 4, off -1)
__global__ void smooth_kernel(int ssel, int dsel,
                              const float* __restrict__ x0,
                              const float* __restrict__ b,
                              float* __restrict__ outp) {
    const float* __restrict__ xin = sel_src(ssel, x0, outp);
    float* __restrict__ xout = sel_dst(dsel, outp);
    int i = blockIdx.x * blockDim.x + threadIdx.x;
    if (i >= NROW) return;
    int c = i & (SDIM - 1);
    float xc = xin[i];
    float s = 4.0f * xc;
    if (c != 0)          s -= xin[i - 1];
    if (c != SDIM - 1)   s -= xin[i + 1];
    if (i >= SDIM)       s -= xin[i - SDIM];
    if (i < NROW - SDIM) s -= xin[i + SDIM];
    xout[i] = xc + WDI * (b[i] - s);
}

// ---------------- fused prolong + smooth ----------------
// x' = x + P ec (reconstructed analytically at all 5 stencil points),
// then one weighted-Jacobi sweep on x'. Removes the separate prolong pass.
__device__ __forceinline__ float corrected(const float* __restrict__ x,
                                           const float2* __restrict__ pv,
                                           int j) {
    float2 p = pv[j];
    int bj = j >> 9;
    float e0 = g_ec[bj];
    float e1 = g_ec[min(bj + 1, NCOL - 1)];
    return x[j] + (p.x * e0 + p.y * e1);
}

__global__ void prolong_smooth_kernel(int ssel, int dsel,
                                      const float* __restrict__ x0,
                                      const float* __restrict__ b,
                                      const float2* __restrict__ pv,
                                      float* __restrict__ outp) {
    const float* __restrict__ xin = sel_src(ssel, x0, outp);
    float* __restrict__ xout = sel_dst(dsel, outp);
    int i = blockIdx.x * blockDim.x + threadIdx.x;
    if (i >= NROW) return;
    int c = i & (SDIM - 1);
    float xc = corrected(xin, pv, i);
    float s = 4.0f * xc;
    if (c != 0)          s -= corrected(xin, pv, i - 1);
    if (c != SDIM - 1)   s -= corrected(xin, pv, i + 1);
    if (i >= SDIM)       s -= corrected(xin, pv, i - SDIM);
    if (i < NROW - SDIM) s -= corrected(xin, pv, i + SDIM);
    xout[i] = xc + WDI * (b[i] - s);
}

// ---------------- fused residual + restriction ----------------
// r = b - A x ;  rc0[c] = sum_{i in block c} pv0[i]*r[i] ; rc1[c] likewise pv1.
// Coarse rhs assembled later as rc[c] = rc0[c] + rc1[c-1] (+ rc1[2047] fold).
__global__ void resid_restrict_kernel(int ssel,
                                      const float* __restrict__ x0,
                                      const float* __restrict__ b,
                                      const float2* __restrict__ pv,
                                      const float* __restrict__ outp) {
    const float* __restrict__ x = sel_src(ssel, x0, outp);
    int blk = blockIdx.x;            // coarse dof / fine block of 512
    int t = threadIdx.x;             // 512 threads
    int i = (blk << 9) + t;
    int c = i & (SDIM - 1);
    float xc = x[i];
    float s = 4.0f * xc;
    if (c != 0)          s -= x[i - 1];
    if (c != SDIM - 1)   s -= x[i + 1];
    if (i >= SDIM)       s -= x[i - SDIM];
    if (i < NROW - SDIM) s -= x[i + SDIM];
    float r = b[i] - s;
    float2 p = pv[i];
    float s0 = p.x * r, s1 = p.y * r;

    // block reduction (16 warps)
    #pragma unroll
    for (int off = 16; off; off >>= 1) {
        s0 += __shfl_xor_sync(0xffffffffu, s0, off);
        s1 += __shfl_xor_sync(0xffffffffu, s1, off);
    }
    __shared__ float sm0[16], sm1[16];
    int w = t >> 5, l = t & 31;
    if (l == 0) { sm0[w] = s0; sm1[w] = s1; }
    __syncthreads();
    if (w == 0) {
        s0 = (l < 16) ? sm0[l] : 0.0f;
        s1 = (l < 16) ? sm1[l] : 0.0f;
        #pragma unroll
        for (int off = 8; off; off >>= 1) {
            s0 += __shfl_xor_sync(0xffffffffu, s0, off);
            s1 += __shfl_xor_sync(0xffffffffu, s1, off);
        }
        if (l == 0) { g_rc0[blk] = s0; g_rc1[blk] = s1; }
    }
}

// ---------------- A_c = P^T A P, banded (offsets -3..+3) ----------------
__global__ void zero_band_kernel() {
    int k = blockIdx.x * blockDim.x + threadIdx.x;
    if (k < NCOL * NBAND) g_band[k] = 0.0f;
}

// scatter into 6-slot register array with compile-time predication (stays in regs)
__device__ __forceinline__ void scat6(float* a, int idx, float v) {
    #pragma unroll
    for (int k = 0; k < 6; ++k)
        if (idx == k) a[k] += v;
}

__global__ void build_band_kernel(const float2* __restrict__ pv) {
    int bi = blockIdx.x;             // fine block / coarse row anchor
    int t = threadIdx.x;             // 512 threads, one fine row each
    int i = (bi << 9) + t;
    int c = i & (SDIM - 1);
    float2 pr = pv[i];
    int base = bi - 2;               // column window [bi-2, bi+3]

    float r0[6], r1[6];              // coarse rows bi and bi+1 (folded at write)
    #pragma unroll
    for (int k = 0; k < 6; ++k) { r0[k] = 0.0f; r1[k] = 0.0f; }

    auto addj = [&](int j, float a) {
        float2 q = pv[j];
        int bj = j >> 9;
        int d0 = bj - base;
        int d1 = min(bj + 1, NCOL - 1) - base;
        float a0 = a * pr.x, a1 = a * pr.y;
        scat6(r0, d0, a0 * q.x); scat6(r0, d1, a0 * q.y);
        scat6(r1, d0, a1 * q.x); scat6(r1, d1, a1 * q.y);
    };
    addj(i, 4.0f);
    if (c != 0)          addj(i - 1, -1.0f);
    if (c != SDIM - 1)   addj(i + 1, -1.0f);
    if (i >= SDIM)       addj(i - SDIM, -1.0f);
    if (i < NROW - SDIM) addj(i + SDIM, -1.0f);

    // warp-shuffle reduce the 12 accumulators
    #pragma unroll
    for (int k = 0; k < 6; ++k) {
        #pragma unroll
        for (int off = 16; off; off >>= 1) {
            r0[k] += __shfl_xor_sync(0xffffffffu, r0[k], off);
            r1[k] += __shfl_xor_sync(0xffffffffu, r1[k], off);
        }
    }
    __shared__ float sm[12];
    if (t < 12) sm[t] = 0.0f;
    __syncthreads();
    if ((t & 31) == 0) {
        #pragma unroll
        for (int k = 0; k < 6; ++k) {
            atomicAdd(&sm[k], r0[k]);
            atomicAdd(&sm[6 + k], r1[k]);
        }
    }
    __syncthreads();
    if (t < 12) {
        int rl = t / 6, cl = t % 6;
        int r = min(bi + rl, NCOL - 1);  // fold row 2048 -> 2047 (clamped P column)
        int d = base + cl;
        if (d >= 0 && d < NCOL) {
            int o = d - r + 3;
            if (o >= 0 && o <= 6)
                atomicAdd(&g_band[r * NBAND + o], sm[t]);
        }
    }
}

// ---------------- coarse solve: 10 weighted-Jacobi sweeps on banded A_c -------
// Band coefficients live in registers (2 rows x 7 per thread); only the ec
// vector is in (static) shared memory. No dynamic smem, no attribute calls.
__global__ void coarse_solve_kernel() {
    __shared__ float s_ec[NCOL + 6];        // 3-cell zero pad each side
    int t = threadIdx.x;                    // 1024 threads, 2 dofs each

    float bnd[2][NBAND];
    #pragma unroll
    for (int h = 0; h < 2; ++h) {
        int cc = t + h * 1024;
        #pragma unroll
        for (int k = 0; k < NBAND; ++k)
            bnd[h][k] = g_band[cc * NBAND + k];
    }

    s_ec[3 + t] = 0.0f;
    s_ec[3 + t + 1024] = 0.0f;
    if (t < 3) { s_ec[t] = 0.0f; s_ec[NCOL + 3 + t] = 0.0f; }
    __syncthreads();

    float rcv[2], dinv[2];
    #pragma unroll
    for (int h = 0; h < 2; ++h) {
        int cc = t + h * 1024;
        float rc = g_rc0[cc];
        if (cc > 0)         rc += g_rc1[cc - 1];
        if (cc == NCOL - 1) rc += g_rc1[cc];   // clamped second P column of last block
        rcv[h] = rc;
        dinv[h] = 1.0f / bnd[h][3];
    }
    for (int it = 0; it < COARSE_IT; ++it) {
        float nv[2];
        #pragma unroll
        for (int h = 0; h < 2; ++h) {
            int cc = t + h * 1024;
            float sum = 0.0f;
            #pragma unroll
            for (int k = 0; k < NBAND; ++k)
                sum += bnd[h][k] * s_ec[cc + k];
            nv[h] = s_ec[cc + 3] + WJ * dinv[h] * (rcv[h] - sum);
        }
        __syncthreads();
        s_ec[3 + t] = nv[0];
        s_ec[3 + t + 1024] = nv[1];
        __syncthreads();
    }
    g_ec[t] = s_ec[3 + t];
    g_ec[t + 1024] = s_ec[3 + t + 1024];
}

// ---------------- orchestration: kernel launches ONLY ----------------
extern "C" void kernel_launch(void* const* d_in, const int* in_sizes, int n_in,
                              void* d_out, int out_size) {
    // input order: b, x, a_val, p_val, a_row, a_col, p_col
    const float*  b  = (const float*)d_in[0];
    const float*  x0 = (const float*)d_in[1];
    const float2* pv = (const float2*)d_in[3];   // (NROW,2) row-major
    float* out = (float*)d_out;

    // Build banded Galerkin coarse operator once per launch
    zero_band_kernel<<<(NCOL * NBAND + 255) / 256, 256>>>();
    build_band_kernel<<<NCOL, 512>>>(pv);

    int cur = 0;        // selector: 0=x0, 1=bufA, 2=bufB, 3=out
    int nxt = 1;        // next ping-pong target (1 or 2)
    for (int cyc = 0; cyc < CYCLES; ++cyc) {
        for (int s = 0; s < SMOOTHS; ++s) {               // pre-smooth
            smooth_kernel<<<NROW / 256, 256>>>(cur, nxt, x0, b, out);
            cur = nxt; nxt = (nxt == 1) ? 2 : 1;
        }
        resid_restrict_kernel<<<NCOL, 512>>>(cur, x0, b, pv, out);
        coarse_solve_kernel<<<1, 1024>>>();

        // post-smooth: first sweep fused with the coarse correction x += P ec
        prolong_smooth_kernel<<<NROW / 256, 256>>>(cur, nxt, x0, b, pv, out);
        cur = nxt; nxt = (nxt == 1) ? 2 : 1;
        for (int s = 1; s < SMOOTHS; ++s) {
            int dsel = (cyc == CYCLES - 1 && s == SMOOTHS - 1) ? 3 : nxt;
            smooth_kernel<<<NROW / 256, 256>>>(cur, dsel, x0, b, out);
            cur = dsel; nxt = (nxt == 1) ? 2 : 1;
        }
    }
}

// round 10
// speedup vs baseline: 1.6219x; 1.6219x over previous
#include <cuda_runtime.h>

#define SDIM 1024
#define NROW (SDIM*SDIM)
#define NCOL 2048
#define NBAND 7
#define CYCLES 10
#define COARSE_IT 10

#define TX 64
#define TY 32

// ---------------- device scratch (no allocation allowed) ----------------
__device__ float g_bufA[NROW];
__device__ float g_bufB[NROW];
__device__ float g_band[NCOL * NBAND];
__device__ float g_part[2][8][NCOL];   // restriction partials: [pv comp][col-tile][coarse dof]
__device__ float g_ec[NCOL];

// W = 2/3 (f32-rounded like the reference), fine dinv = 1/4 exactly
#define WJ ((float)(2.0/3.0))
#define WDI (WJ * 0.25f)

// Buffer selectors: 0 = external input x0, 1 = g_bufA, 2 = g_bufB, 3 = external out
__device__ __forceinline__ const float* sel_src(int s, const float* x0, const float* out) {
    if (s == 0) return x0;
    if (s == 1) return g_bufA;
    if (s == 2) return g_bufB;
    return out;
}
__device__ __forceinline__ float* sel_dst(int s, float* out) {
    if (s == 1) return g_bufA;
    if (s == 2) return g_bufB;
    return out;
}

// ============================================================================
// Fused triple-smooth kernel (temporal blocking), optionally fused with
//   - prolongation applied at load (x += P ec), halo H = 3
//   - residual + restriction at store,        halo H = 4
// Zero padding outside the domain is exactly the clamped 5-point stencil.
// ============================================================================
template<int H, bool DO_RESTRICT, bool DO_PROLONG>
__global__ __launch_bounds__(256) void fused3_kernel(
        int ssel, int dsel,
        const float* __restrict__ x0,
        const float* __restrict__ bg,
        const float2* __restrict__ pv,
        float* __restrict__ outp)
{
    constexpr int NIT = 3;
    constexpr int RX = TX + 2 * H;
    constexpr int RY = TY + 2 * H;
    constexpr int RN = RX * RY;

    __shared__ float sx[2][RN];
    __shared__ float sb[RN];
    __shared__ float rs0[TY], rs1[TY];

    const float* __restrict__ xin = sel_src(ssel, x0, outp);
    float* __restrict__ xout = sel_dst(dsel, outp);

    int tid = threadIdx.x;
    int gx0 = blockIdx.x * TX - H;   // global col of smem origin
    int gy0 = blockIdx.y * TY - H;   // global row of smem origin

    // ---- load region (zero-padded), optional coarse correction ----
    for (int idx = tid; idx < RN; idx += 256) {
        int r = idx / RX, c = idx - r * RX;
        int gr = gy0 + r, gc = gx0 + c;
        float xv = 0.0f, bv = 0.0f;
        if ((unsigned)gr < SDIM && (unsigned)gc < SDIM) {
            int gi = gr * SDIM + gc;
            xv = xin[gi];
            bv = bg[gi];
            if (DO_PROLONG) {
                float2 p = pv[gi];
                int bj = gi >> 9;
                xv += p.x * g_ec[bj] + p.y * g_ec[min(bj + 1, NCOL - 1)];
            }
        }
        sx[0][idx] = xv;
        sb[idx] = bv;
    }
    if (DO_RESTRICT && tid < TY) { rs0[tid] = 0.0f; rs1[tid] = 0.0f; }
    __syncthreads();

    // ---- 3 Jacobi sweeps in shared memory (double buffer, ring copy) ----
    int cur = 0;
    #pragma unroll
    for (int it = 0; it < NIT; ++it) {
        for (int idx = tid; idx < RN; idx += 256) {
            int r = idx / RX, c = idx - r * RX;
            float xc = sx[cur][idx];
            float v = xc;
            int gr = gy0 + r, gc = gx0 + c;
            if (r > 0 && r < RY - 1 && c > 0 && c < RX - 1 &&
                (unsigned)gr < SDIM && (unsigned)gc < SDIM) {
                float s = 4.0f * xc - sx[cur][idx - 1] - sx[cur][idx + 1]
                                    - sx[cur][idx - RX] - sx[cur][idx + RX];
                v = xc + WDI * (sb[idx] - s);
            }
            sx[cur ^ 1][idx] = v;
        }
        __syncthreads();
        cur ^= 1;
    }

    // ---- store core tile; optional residual + restriction ----
    for (int idx = tid; idx < TY * TX; idx += 256) {
        int r = idx >> 6, c = idx & 63;          // TX = 64
        int si = (r + H) * RX + (c + H);
        int gi = (gy0 + H + r) * SDIM + (gx0 + H + c);
        float xc = sx[cur][si];
        xout[gi] = xc;
        if (DO_RESTRICT) {
            float s = 4.0f * xc - sx[cur][si - 1] - sx[cur][si + 1]
                                - sx[cur][si - RX] - sx[cur][si + RX];
            float rres = sb[si] - s;
            float2 p = pv[gi];
            float v0 = p.x * rres, v1 = p.y * rres;
            // warp covers one half-row (r constant per warp) -> shuffle reduce
            #pragma unroll
            for (int off = 16; off; off >>= 1) {
                v0 += __shfl_xor_sync(0xffffffffu, v0, off);
                v1 += __shfl_xor_sync(0xffffffffu, v1, off);
            }
            if ((tid & 31) == 0) {               // 2 commutative adds per slot
                atomicAdd(&rs0[r], v0);
                atomicAdd(&rs1[r], v1);
            }
        }
    }
    if (DO_RESTRICT) {
        __syncthreads();
        if (tid < TY) {
            int gr = gy0 + H + tid;
            int side = (blockIdx.x >= (512 / TX)) ? 1 : 0;
            int dof = 2 * gr + side;             // coarse dof this fine row feeds
            int j = blockIdx.x & 7;              // exclusive partial slot
            g_part[0][j][dof] = rs0[tid];
            g_part[1][j][dof] = rs1[tid];
        }
    }
}

// ---------------- A_c = P^T A P, banded (offsets -3..+3) ----------------
__global__ void zero_band_kernel() {
    int k = blockIdx.x * blockDim.x + threadIdx.x;
    if (k < NCOL * NBAND) g_band[k] = 0.0f;
}

__device__ __forceinline__ void scat6(float* a, int idx, float v) {
    #pragma unroll
    for (int k = 0; k < 6; ++k)
        if (idx == k) a[k] += v;
}

__global__ void build_band_kernel(const float2* __restrict__ pv) {
    int bi = blockIdx.x;             // fine block / coarse row anchor
    int t = threadIdx.x;             // 512 threads, one fine row each
    int i = (bi << 9) + t;
    int c = i & (SDIM - 1);
    float2 pr = pv[i];
    int base = bi - 2;               // column window [bi-2, bi+3]

    float r0[6], r1[6];              // coarse rows bi and bi+1 (folded at write)
    #pragma unroll
    for (int k = 0; k < 6; ++k) { r0[k] = 0.0f; r1[k] = 0.0f; }

    auto addj = [&](int j, float a) {
        float2 q = pv[j];
        int bj = j >> 9;
        int d0 = bj - base;
        int d1 = min(bj + 1, NCOL - 1) - base;
        float a0 = a * pr.x, a1 = a * pr.y;
        scat6(r0, d0, a0 * q.x); scat6(r0, d1, a0 * q.y);
        scat6(r1, d0, a1 * q.x); scat6(r1, d1, a1 * q.y);
    };
    addj(i, 4.0f);
    if (c != 0)          addj(i - 1, -1.0f);
    if (c != SDIM - 1)   addj(i + 1, -1.0f);
    if (i >= SDIM)       addj(i - SDIM, -1.0f);
    if (i < NROW - SDIM) addj(i + SDIM, -1.0f);

    #pragma unroll
    for (int k = 0; k < 6; ++k) {
        #pragma unroll
        for (int off = 16; off; off >>= 1) {
            r0[k] += __shfl_xor_sync(0xffffffffu, r0[k], off);
            r1[k] += __shfl_xor_sync(0xffffffffu, r1[k], off);
        }
    }
    __shared__ float sm[12];
    if (t < 12) sm[t] = 0.0f;
    __syncthreads();
    if ((t & 31) == 0) {
        #pragma unroll
        for (int k = 0; k < 6; ++k) {
            atomicAdd(&sm[k], r0[k]);
            atomicAdd(&sm[6 + k], r1[k]);
        }
    }
    __syncthreads();
    if (t < 12) {
        int rl = t / 6, cl = t % 6;
        int r = min(bi + rl, NCOL - 1);  // fold row 2048 -> 2047 (clamped P column)
        int d = base + cl;
        if (d >= 0 && d < NCOL) {
            int o = d - r + 3;
            if (o >= 0 && o <= 6)
                atomicAdd(&g_band[r * NBAND + o], sm[t]);
        }
    }
}

// ---------------- coarse solve: assemble rc from partials, 10 Jacobi sweeps --
__global__ void coarse_solve_kernel() {
    __shared__ float s_ec[NCOL + 6];        // 3-cell zero pad each side
    int t = threadIdx.x;                    // 1024 threads, 2 dofs each

    float bnd[2][NBAND];
    #pragma unroll
    for (int h = 0; h < 2; ++h) {
        int cc = t + h * 1024;
        #pragma unroll
        for (int k = 0; k < NBAND; ++k)
            bnd[h][k] = g_band[cc * NBAND + k];
    }

    s_ec[3 + t] = 0.0f;
    s_ec[3 + t + 1024] = 0.0f;
    if (t < 3) { s_ec[t] = 0.0f; s_ec[NCOL + 3 + t] = 0.0f; }
    __syncthreads();

    float rcv[2], dinv[2];
    #pragma unroll
    for (int h = 0; h < 2; ++h) {
        int cc = t + h * 1024;
        float rc = 0.0f;
        #pragma unroll
        for (int j = 0; j < 8; ++j) rc += g_part[0][j][cc];
        if (cc > 0) {
            #pragma unroll
            for (int j = 0; j < 8; ++j) rc += g_part[1][j][cc - 1];
        }
        if (cc == NCOL - 1) {                 // clamped second P column fold
            #pragma unroll
            for (int j = 0; j < 8; ++j) rc += g_part[1][j][cc];
        }
        rcv[h] = rc;
        dinv[h] = 1.0f / bnd[h][3];
    }
    for (int it = 0; it < COARSE_IT; ++it) {
        float nv[2];
        #pragma unroll
        for (int h = 0; h < 2; ++h) {
            int cc = t + h * 1024;
            float sum = 0.0f;
            #pragma unroll
            for (int k = 0; k < NBAND; ++k)
                sum += bnd[h][k] * s_ec[cc + k];
            nv[h] = s_ec[cc + 3] + WJ * dinv[h] * (rcv[h] - sum);
        }
        __syncthreads();
        s_ec[3 + t] = nv[0];
        s_ec[3 + t + 1024] = nv[1];
        __syncthreads();
    }
    g_ec[t] = s_ec[3 + t];
    g_ec[t + 1024] = s_ec[3 + t + 1024];
}

// ---------------- orchestration: kernel launches ONLY ----------------
extern "C" void kernel_launch(void* const* d_in, const int* in_sizes, int n_in,
                              void* d_out, int out_size) {
    // input order: b, x, a_val, p_val, a_row, a_col, p_col
    const float*  b  = (const float*)d_in[0];
    const float*  x0 = (const float*)d_in[1];
    const float2* pv = (const float2*)d_in[3];   // (NROW,2) row-major
    float* out = (float*)d_out;

    // Build banded Galerkin coarse operator once per launch
    zero_band_kernel<<<(NCOL * NBAND + 255) / 256, 256>>>();
    build_band_kernel<<<NCOL, 512>>>(pv);

    dim3 grid(SDIM / TX, SDIM / TY);
    for (int cyc = 0; cyc < CYCLES; ++cyc) {
        int src = (cyc == 0) ? 0 : 2;            // x0 first, then bufB
        // 3 pre-smooths + residual + restriction  (-> bufA, partials)
        fused3_kernel<4, true, false><<<grid, 256>>>(src, 1, x0, b, pv, out);
        // coarse Jacobi solve -> g_ec
        coarse_solve_kernel<<<1, 1024>>>();
        // prolong + 3 post-smooths (-> bufB, or out on last cycle)
        int dst = (cyc == CYCLES - 1) ? 3 : 2;
        fused3_kernel<3, false, true><<<grid, 256>>>(1, dst, x0, b, pv, out);
    }
}

// round 12
// speedup vs baseline: 1.7009x; 1.0487x over previous
#include <cuda_runtime.h>

#define SDIM 1024
#define NROW (SDIM*SDIM)
#define NCOL 2048
#define NBAND 7
#define CYCLES 10
#define NDIAG 61            // coarse polynomial operator band: offsets -30..+30

#define TX 64
#define TY 32

// ---------------- device scratch (no allocation allowed) ----------------
__device__ float g_bufA[NROW];
__device__ float g_bufB[NROW];
__device__ float g_band[NCOL * NBAND];
__device__ float g_part[2][8][NCOL];   // restriction partials: [pv comp][col-tile][coarse dof]
__device__ float g_ec[NCOL];
__device__ float g_g[7 * NCOL];        // G = I - W D^-1 A_c, diagonals -3..+3
__device__ float g_Hd[NCOL];           // H = W D^-1
__device__ float g_C0[NDIAG * NCOL];   // polynomial operator, diagonal storage [o][c]
__device__ float g_C1[NDIAG * NCOL];

// W = 2/3 (f32-rounded like the reference), fine dinv = 1/4 exactly
#define WJ ((float)(2.0/3.0))
#define WDI (WJ * 0.25f)

// Buffer selectors: 0 = external input x0, 1 = g_bufA, 2 = g_bufB, 3 = external out
__device__ __forceinline__ const float* sel_src(int s, const float* x0, const float* out) {
    if (s == 0) return x0;
    if (s == 1) return g_bufA;
    if (s == 2) return g_bufB;
    return out;
}
__device__ __forceinline__ float* sel_dst(int s, float* out) {
    if (s == 1) return g_bufA;
    if (s == 2) return g_bufB;
    return out;
}

// ============================================================================
// Fused NIT-sweep smooth kernel (temporal blocking), optionally fused with
//   - prolongation applied at load (x += P ec)
//   - residual + restriction at store (needs H = NIT + 1)
// Zero padding outside the domain is exactly the clamped 5-point stencil.
// ============================================================================
template<int H, int NIT, bool DO_RESTRICT, bool DO_PROLONG>
__global__ __launch_bounds__(256) void fusedN_kernel(
        int ssel, int dsel,
        const float* __restrict__ x0,
        const float* __restrict__ bg,
        const float2* __restrict__ pv,
        float* __restrict__ outp)
{
    constexpr int RX = TX + 2 * H;
    constexpr int RY = TY + 2 * H;
    constexpr int RN = RX * RY;

    __shared__ float sx[2][RN];
    __shared__ float sb[RN];
    __shared__ float rs0[TY], rs1[TY];

    const float* __restrict__ xin = sel_src(ssel, x0, outp);
    float* __restrict__ xout = sel_dst(dsel, outp);

    int tid = threadIdx.x;
    int gx0 = blockIdx.x * TX - H;   // global col of smem origin
    int gy0 = blockIdx.y * TY - H;   // global row of smem origin

    // ---- load region (zero-padded), optional coarse correction ----
    for (int idx = tid; idx < RN; idx += 256) {
        int r = idx / RX, c = idx - r * RX;
        int gr = gy0 + r, gc = gx0 + c;
        float xv = 0.0f, bv = 0.0f;
        if ((unsigned)gr < SDIM && (unsigned)gc < SDIM) {
            int gi = gr * SDIM + gc;
            xv = xin[gi];
            bv = bg[gi];
            if (DO_PROLONG) {
                float2 p = pv[gi];
                int bj = gi >> 9;
                xv += p.x * g_ec[bj] + p.y * g_ec[min(bj + 1, NCOL - 1)];
            }
        }
        sx[0][idx] = xv;
        sb[idx] = bv;
    }
    if (DO_RESTRICT && tid < TY) { rs0[tid] = 0.0f; rs1[tid] = 0.0f; }
    __syncthreads();

    // ---- NIT Jacobi sweeps in shared memory (double buffer) ----
    int cur = 0;
    #pragma unroll
    for (int it = 0; it < NIT; ++it) {
        for (int idx = tid; idx < RN; idx += 256) {
            int r = idx / RX, c = idx - r * RX;
            float xc = sx[cur][idx];
            float v = xc;
            int gr = gy0 + r, gc = gx0 + c;
            if (r > 0 && r < RY - 1 && c > 0 && c < RX - 1 &&
                (unsigned)gr < SDIM && (unsigned)gc < SDIM) {
                float s = 4.0f * xc - sx[cur][idx - 1] - sx[cur][idx + 1]
                                    - sx[cur][idx - RX] - sx[cur][idx + RX];
                v = xc + WDI * (sb[idx] - s);
            }
            sx[cur ^ 1][idx] = v;
        }
        __syncthreads();
        cur ^= 1;
    }

    // ---- store core tile; optional residual + restriction ----
    for (int idx = tid; idx < TY * TX; idx += 256) {
        int r = idx >> 6, c = idx & 63;          // TX = 64
        int si = (r + H) * RX + (c + H);
        int gi = (gy0 + H + r) * SDIM + (gx0 + H + c);
        float xc = sx[cur][si];
        xout[gi] = xc;
        if (DO_RESTRICT) {
            float s = 4.0f * xc - sx[cur][si - 1] - sx[cur][si + 1]
                                - sx[cur][si - RX] - sx[cur][si + RX];
            float rres = sb[si] - s;
            float2 p = pv[gi];
            float v0 = p.x * rres, v1 = p.y * rres;
            // warp covers one half-row (r constant per warp) -> shuffle reduce
            #pragma unroll
            for (int off = 16; off; off >>= 1) {
                v0 += __shfl_xor_sync(0xffffffffu, v0, off);
                v1 += __shfl_xor_sync(0xffffffffu, v1, off);
            }
            if ((tid & 31) == 0) {               // 2 commutative adds per slot
                atomicAdd(&rs0[r], v0);
                atomicAdd(&rs1[r], v1);
            }
        }
    }
    if (DO_RESTRICT) {
        __syncthreads();
        if (tid < TY) {
            int gr = gy0 + H + tid;
            int side = (blockIdx.x >= (512 / TX)) ? 1 : 0;
            int dof = 2 * gr + side;             // coarse dof this fine row feeds
            int j = blockIdx.x & 7;              // exclusive partial slot
            g_part[0][j][dof] = rs0[tid];
            g_part[1][j][dof] = rs1[tid];
        }
    }
}

// ---------------- A_c = P^T A P, banded (offsets -3..+3) ----------------
__global__ void zero_band_kernel() {
    int k = blockIdx.x * blockDim.x + threadIdx.x;
    if (k < NCOL * NBAND) g_band[k] = 0.0f;
}

__device__ __forceinline__ void scat6(float* a, int idx, float v) {
    #pragma unroll
    for (int k = 0; k < 6; ++k)
        if (idx == k) a[k] += v;
}

__global__ void build_band_kernel(const float2* __restrict__ pv) {
    int bi = blockIdx.x;             // fine block / coarse row anchor
    int t = threadIdx.x;             // 512 threads, one fine row each
    int i = (bi << 9) + t;
    int c = i & (SDIM - 1);
    float2 pr = pv[i];
    int base = bi - 2;               // column window [bi-2, bi+3]

    float r0[6], r1[6];              // coarse rows bi and bi+1 (folded at write)
    #pragma unroll
    for (int k = 0; k < 6; ++k) { r0[k] = 0.0f; r1[k] = 0.0f; }

    auto addj = [&](int j, float a) {
        float2 q = pv[j];
        int bj = j >> 9;
        int d0 = bj - base;
        int d1 = min(bj + 1, NCOL - 1) - base;
        float a0 = a * pr.x, a1 = a * pr.y;
        scat6(r0, d0, a0 * q.x); scat6(r0, d1, a0 * q.y);
        scat6(r1, d0, a1 * q.x); scat6(r1, d1, a1 * q.y);
    };
    addj(i, 4.0f);
    if (c != 0)          addj(i - 1, -1.0f);
    if (c != SDIM - 1)   addj(i + 1, -1.0f);
    if (i >= SDIM)       addj(i - SDIM, -1.0f);
    if (i < NROW - SDIM) addj(i + SDIM, -1.0f);

    #pragma unroll
    for (int k = 0; k < 6; ++k) {
        #pragma unroll
        for (int off = 16; off; off >>= 1) {
            r0[k] += __shfl_xor_sync(0xffffffffu, r0[k], off);
            r1[k] += __shfl_xor_sync(0xffffffffu, r1[k], off);
        }
    }
    __shared__ float sm[12];
    if (t < 12) sm[t] = 0.0f;
    __syncthreads();
    if ((t & 31) == 0) {
        #pragma unroll
        for (int k = 0; k < 6; ++k) {
            atomicAdd(&sm[k], r0[k]);
            atomicAdd(&sm[6 + k], r1[k]);
        }
    }
    __syncthreads();
    if (t < 12) {
        int rl = t / 6, cl = t % 6;
        int r = min(bi + rl, NCOL - 1);  // fold row 2048 -> 2047 (clamped P column)
        int d = base + cl;
        if (d >= 0 && d < NCOL) {
            int o = d - r + 3;
            if (o >= 0 && o <= 6)
                atomicAdd(&g_band[r * NBAND + o], sm[t]);
        }
    }
}

// ---------------- coarse polynomial operator build ----------------
// ec after 10 damped-Jacobi sweeps = C rc with C = sum_{j=0..9} G^j H,
// G = I - W D^-1 A_c (band +-3), H = W D^-1. C has band <= +-27 (stored +-30).
__global__ void make_g_kernel() {
    int c = blockIdx.x * blockDim.x + threadIdx.x;
    if (c >= NCOL) return;
    float dinv = 1.0f / g_band[c * NBAND + 3];
    g_Hd[c] = WJ * dinv;
    #pragma unroll
    for (int d = 0; d < 7; ++d)
        g_g[d * NCOL + c] = ((d == 3) ? 1.0f : 0.0f) - WJ * dinv * g_band[c * NBAND + d];
}

__global__ void zero_C_kernel() {
    int k = blockIdx.x * blockDim.x + threadIdx.x;
    if (k < NDIAG * NCOL) g_C0[k] = 0.0f;
}

// C_{k+1} = G C_k + H  in diagonal storage: new[o][c] = (o==30)H[c]
//   + sum_{d=-3..3} g[c][d] * old[o-d][c+d]
__global__ void iterC_kernel(int srcsel) {
    const float* __restrict__ src = srcsel ? g_C1 : g_C0;
    float* __restrict__ dst = srcsel ? g_C0 : g_C1;
    int idx = blockIdx.x * blockDim.x + threadIdx.x;   // o = idx/NCOL, c = idx%NCOL
    if (idx >= NDIAG * NCOL) return;
    int o = idx >> 11, c = idx & (NCOL - 1);
    float acc = (o == 30) ? g_Hd[c] : 0.0f;
    #pragma unroll
    for (int dd = 0; dd < 7; ++dd) {
        int d = dd - 3;
        int oo = o - d, cc = c + d;
        if (oo >= 0 && oo < NDIAG && cc >= 0 && cc < NCOL)
            acc += g_g[dd * NCOL + c] * src[oo * NCOL + cc];
    }
    dst[idx] = acc;
}

// ---------------- coarse apply: ec = C rc (rc assembled from partials) -------
__global__ void apply_coarse_kernel() {    // grid 16, block 128
    __shared__ float s_rc[128 + NDIAG - 1];   // rc window [base-30, base+157]
    int bi = blockIdx.x, t = threadIdx.x;
    int base = bi * 128;
    for (int k = t; k < 128 + NDIAG - 1; k += 128) {
        int cc = base - 30 + k;
        float v = 0.0f;
        if (cc >= 0 && cc < NCOL) {
            #pragma unroll
            for (int j = 0; j < 8; ++j) v += g_part[0][j][cc];
            if (cc > 0) {
                #pragma unroll
                for (int j = 0; j < 8; ++j) v += g_part[1][j][cc - 1];
            }
            if (cc == NCOL - 1) {            // clamped second P column fold
                #pragma unroll
                for (int j = 0; j < 8; ++j) v += g_part[1][j][cc];
            }
        }
        s_rc[k] = v;
    }
    __syncthreads();
    int c = base + t;
    float sum = 0.0f;
    #pragma unroll
    for (int o = 0; o < NDIAG; ++o)
        sum += g_C0[o * NCOL + c] * s_rc[t + o];
    g_ec[c] = sum;
}

// ---------------- orchestration: kernel launches ONLY ----------------
extern "C" void kernel_launch(void* const* d_in, const int* in_sizes, int n_in,
                              void* d_out, int out_size) {
    // input order: b, x, a_val, p_val, a_row, a_col, p_col
    const float*  b  = (const float*)d_in[0];
    const float*  x0 = (const float*)d_in[1];
    const float2* pv = (const float2*)d_in[3];   // (NROW,2) row-major
    float* out = (float*)d_out;

    // Build banded Galerkin coarse operator + polynomial solve operator C
    zero_band_kernel<<<(NCOL * NBAND + 255) / 256, 256>>>();
    build_band_kernel<<<NCOL, 512>>>(pv);
    make_g_kernel<<<NCOL / 256, 256>>>();
    zero_C_kernel<<<(NDIAG * NCOL + 255) / 256, 256>>>();
    for (int k = 0; k < 10; ++k)                 // last iter writes g_C0
        iterC_kernel<<<(NDIAG * NCOL + 255) / 256, 256>>>(k & 1);

    dim3 grid(SDIM / TX, SDIM / TY);
    // cycle 0 pre-smooth (3) + restrict:  x0 -> bufA
    fusedN_kernel<4, 3, true, false><<<grid, 256>>>(0, 1, x0, b, pv, out);

    // 9 merged kernels: prolong + post3(k) + pre3(k+1) + restrict
    for (int k = 0; k < 9; ++k) {
        apply_coarse_kernel<<<16, 128>>>();
        int src = (k & 1) ? 2 : 1;               // A,B alternate
        int dst = (k & 1) ? 1 : 2;
        fusedN_kernel<7, 6, true, true><<<grid, 256>>>(src, dst, x0, b, pv, out);
    }

    // final: coarse apply + prolong + post3 -> out   (after k=8: result in bufB)
    apply_coarse_kernel<<<16, 128>>>();
    fusedN_kernel<3, 3, false, true><<<grid, 256>>>(2, 3, x0, b, pv, out);
}